// round 12
// baseline (speedup 1.0000x reference)
#include <cuda_runtime.h>
#include <cuda_fp16.h>
#include <cstdint>

// ---------------- problem constants ----------------
#define B_     64
#define CIN_   64
#define L_     4096
#define COUT_  128
#define K_     7
#define LOUT_  2048

// ---------------- GEMM tiling ----------------
#define TILE_L  256                 // l positions per CTA tile (4096/256 = 16 exact)
#define LT_PB   16
#define NTILES  (B_ * LT_PB)        // 1024
#define ROWS    262                 // TILE_L + 6 halo
#define NTHR    512                 // 16 warps: 4 cout quarters x 4 l quarters
#define GRID    148

// ---------------- smem layout (kernel 2) ----------------
// A: weights 7 x [128 cout x 64 cin] fp16, 128B rows + SW128 XOR swizzle.
// B: sign tile x2 ping-pong, [262 l-rows x 64 cin] fp16, stride 72 halfs
//    (144B) -> ldmatrix row addrs 4 banks apart: conflict-free.
#define SB_STRIDE 72
#define SM_A      0
#define SM_A_SZ   (K_ * COUT_ * CIN_ * 2)     // 114688
#define SM_B      SM_A_SZ
#define SB_BUF    (ROWS * SB_STRIDE * 2)      // 37728
#define SM_TOTAL  (SM_B + 2 * SB_BUF + 32)    // 190176

// 32MB sign scratch: [b][l][cin] fp16, rows of 128B
__device__ __half g_sign[(size_t)B_ * L_ * CIN_];

// ---------------- PTX helpers ----------------
__device__ __forceinline__ uint32_t smem_u32(const void* p) {
    uint32_t a;
    asm("{ .reg .u64 t; cvta.to.shared.u64 t, %1; cvt.u32.u64 %0, t; }"
        : "=r"(a) : "l"(p));
    return a;
}
__device__ __forceinline__ void ldsm4(uint32_t* r, uint32_t a) {
    asm volatile("ldmatrix.sync.aligned.m8n8.x4.shared.b16 {%0,%1,%2,%3}, [%4];"
        : "=r"(r[0]), "=r"(r[1]), "=r"(r[2]), "=r"(r[3]) : "r"(a));
}
__device__ __forceinline__ void mma16816(float* d,
                                         uint32_t a0, uint32_t a1, uint32_t a2, uint32_t a3,
                                         uint32_t b0, uint32_t b1) {
    asm volatile("mma.sync.aligned.m16n8k16.row.col.f32.f16.f16.f32 "
                 "{%0,%1,%2,%3}, {%4,%5,%6,%7}, {%8,%9}, {%0,%1,%2,%3};"
                 : "+f"(d[0]), "+f"(d[1]), "+f"(d[2]), "+f"(d[3])
                 : "r"(a0), "r"(a1), "r"(a2), "r"(a3), "r"(b0), "r"(b1));
}
__device__ __forceinline__ void cp16(uint32_t dst, const void* src, int sz) {
    asm volatile("cp.async.cg.shared.global [%0], [%1], 16, %2;"
                 :: "r"(dst), "l"(src), "r"(sz) : "memory");
}
#define CP_COMMIT() asm volatile("cp.async.commit_group;" ::: "memory")
#define CP_WAIT0()  asm volatile("cp.async.wait_group 0;" ::: "memory")
// XOR swizzle on byte offsets within A (128B rows)
__device__ __forceinline__ uint32_t swA(uint32_t o) { return o ^ ((o >> 3) & 0x70); }

// ============ kernel 1: BN + sign + transpose -> g_sign[b][l][cin] ============
__global__ __launch_bounds__(256)
void bn_sign_kernel(const float* __restrict__ I,
                    const float* __restrict__ bn_gamma,
                    const float* __restrict__ bn_beta,
                    const float* __restrict__ bn_mean,
                    const float* __restrict__ bn_var)
{
    __shared__ float sa[CIN_], sb[CIN_];
    __shared__ __half st[128][66];       // pad 66 -> conflict-free both phases

    const int tid = threadIdx.x;
    const int b   = blockIdx.y;
    const int l0  = blockIdx.x << 7;     // 128 l per block

    if (tid < CIN_) {
        float a = bn_gamma[tid] * rsqrtf(bn_var[tid] + 1e-5f);
        sa[tid] = a;
        sb[tid] = bn_beta[tid] - bn_mean[tid] * a;
    }
    __syncthreads();

    // phase 1: read I[b][cin][l0+ll] (coalesced in ll), sign -> st[ll][cin]
    #pragma unroll
    for (int it = 0; it < 32; it++) {
        int idx = tid + it * 256;        // 8192 = 64cin x 128l
        int ll  = idx & 127;
        int cin = idx >> 7;
        float v = I[((size_t)b * CIN_ + cin) * L_ + l0 + ll];
        float x = fmaf(sa[cin], v, sb[cin]);
        float s = (x > 0.f) ? 1.f : ((x < 0.f) ? -1.f : 0.f);
        st[ll][cin] = __float2half(s);
    }
    __syncthreads();

    // phase 2: write g_sign[b][l0+ll][cin], 4B per thread, coalesced
    uint32_t* gs = (uint32_t*)g_sign;
    #pragma unroll
    for (int it = 0; it < 16; it++) {
        int idx = tid + it * 256;        // 4096 u32 = 128l x 32
        int ll  = idx >> 5;
        int cp  = idx & 31;
        uint32_t val = *(const uint32_t*)&st[ll][cp * 2];
        gs[((size_t)b * L_ + l0 + ll) * 32 + cp] = val;
    }
}

// ============ kernel 2: persistent GEMM + fused epilogue ============
// 16 warps, warp tile = 32 cout x 64 l (mf=2, nf=8). Sign tiles arrive via
// cp.async directly in ldmatrix layout (no convert pass). 1 barrier/tile.
__global__ __launch_bounds__(NTHR, 1)
void conv_gemm_kernel(const float* __restrict__ conv_w,
                      const float* __restrict__ alpha,
                      const float* __restrict__ prelu_w,
                      float* __restrict__ out)
{
    extern __shared__ __align__(16) char smem[];
    const uint32_t sm0 = smem_u32(smem);

    const int tid  = threadIdx.x;
    const int lane = tid & 31;
    const int wid  = tid >> 5;
    const int wc   = wid >> 2;      // cout quarter (0..3): 32 couts
    const int wl   = wid & 3;       // l quarter    (0..3): 64 l
    const int r    = lane >> 2;
    const int q    = lane & 3;

    // Weights -> fp16, [tap][cout][cin] 128B rows, SW128 swizzle (once)
    for (int idx = tid; idx < COUT_ * CIN_ * K_; idx += NTHR) {
        int k    = idx % K_;
        int rest = idx / K_;
        int cin  = rest & (CIN_ - 1);
        int cout = rest >> 6;
        uint32_t off = (uint32_t)((((k * COUT_ + cout) * CIN_) + cin) * 2);
        *(__half*)(smem + SM_A + swA(off)) = __float2half(conv_w[idx]);
    }

    // A ldmatrix lane addressing: tiles (m0-7,k0-7),(m8-15,k0-7),(m0-7,k8-15),(m8-15,k8-15)
    const int jj = lane >> 3, ii = lane & 7;
    const int a_row  = (jj & 1) * 8 + ii;
    const int a_colh = (jj >> 1) * 8;
    // B ldmatrix (non-trans, validated): tiles (n0-7,k0-7),(n0-7,k8-15),(n8-15,k0-7),(n8-15,k8-15)
    const int b_rowc = ((lane >> 4) & 1) * 8 + (lane & 7);  // l row offset
    const int b_kh   = ((lane >> 3) & 1) * 8;               // cin half offset

    float al[2][2];
    #pragma unroll
    for (int mf = 0; mf < 2; mf++) {
        al[mf][0] = alpha[wc * 32 + mf * 16 + r];
        al[mf][1] = alpha[wc * 32 + mf * 16 + r + 8];
    }
    const float pw = prelu_w[0];

    // ---- cp.async: sign rows for tile t -> sB buffer (zfill for halo/OOB) ----
    auto issue_sign = [&](int t, uint32_t sbOff) {
        int bb = t >> 4;
        int l0 = (t & 15) << 8;
        const __half* Sb = g_sign + (size_t)bb * L_ * CIN_;
        #pragma unroll 2
        for (int o = tid; o < ROWS * 8; o += NTHR) {   // 2096 x 16B
            int row = o >> 3, ch = o & 7;
            int gl  = l0 - 3 + row;
            int sz  = ((unsigned)gl < (unsigned)L_) ? 16 : 0;
            int glc = sz ? gl : 0;
            cp16(sm0 + sbOff + (uint32_t)(row * (SB_STRIDE * 2) + ch * 16),
                 Sb + (size_t)glc * CIN_ + ch * 8, sz);
        }
        CP_COMMIT();
    };

    // ---- prologue ----
    issue_sign(blockIdx.x, SM_B);
    __syncthreads();                 // weights visible (cp group still in flight)

    int cur = 0;
    for (int t = blockIdx.x; t < NTILES; t += GRID) {
        const int bb = t >> 4;
        const int l0 = (t & 15) << 8;
        const int tn = t + GRID;

        CP_WAIT0();
        __syncthreads();   // publish sign tile t; also fences tile t-1 reads
        if (tn < NTILES) issue_sign(tn, SM_B + (uint32_t)((cur ^ 1) * SB_BUF));

        const uint32_t sBu = sm0 + SM_B + (uint32_t)(cur * SB_BUF);

        float acc[2][8][4];
        #pragma unroll
        for (int mf = 0; mf < 2; mf++)
            #pragma unroll
            for (int nf = 0; nf < 8; nf++)
                #pragma unroll
                for (int e = 0; e < 4; e++) acc[mf][nf][e] = 0.f;

        #pragma unroll
        for (int k = 0; k < K_; k++) {
            #pragma unroll
            for (int c = 0; c < 4; c++) {
                uint32_t af[2][4];
                #pragma unroll
                for (int mf = 0; mf < 2; mf++) {
                    uint32_t o = (uint32_t)((((k * COUT_ + wc * 32 + mf * 16 + a_row)
                                  * CIN_) + c * 16 + a_colh) * 2);
                    ldsm4(af[mf], sm0 + SM_A + swA(o));
                }
                uint32_t bf[4][4];
                #pragma unroll
                for (int p = 0; p < 4; p++) {
                    uint32_t brow = (uint32_t)(wl * 64 + p * 16 + b_rowc + k);
                    ldsm4(bf[p], sBu + brow * (SB_STRIDE * 2)
                                     + (uint32_t)((c * 16 + b_kh) * 2));
                }
                #pragma unroll
                for (int p = 0; p < 4; p++)
                    #pragma unroll
                    for (int h = 0; h < 2; h++) {
                        uint32_t b0 = bf[p][2 * h], b1 = bf[p][2 * h + 1];
                        #pragma unroll
                        for (int mf = 0; mf < 2; mf++)
                            mma16816(acc[mf][2 * p + h],
                                     af[mf][0], af[mf][1], af[mf][2], af[mf][3],
                                     b0, b1);
                    }
            }
        }

        // epilogue: alpha, PReLU, maxpool(2,2); all tiles full (256 l)
        float* ob = out + ((size_t)bb * COUT_) * LOUT_ + (l0 >> 1);
        #pragma unroll
        for (int mf = 0; mf < 2; mf++) {
            const int c0 = wc * 32 + mf * 16 + r;
            #pragma unroll
            for (int nf = 0; nf < 8; nf++) {
                const int lp = wl * 32 + nf * 4 + q;
                float y0 = acc[mf][nf][0] * al[mf][0];
                float y1 = acc[mf][nf][1] * al[mf][0];
                y0 = (y0 > 0.f) ? y0 : pw * y0;
                y1 = (y1 > 0.f) ? y1 : pw * y1;
                ob[(size_t)c0 * LOUT_ + lp] = fmaxf(y0, y1);
                float y2 = acc[mf][nf][2] * al[mf][1];
                float y3 = acc[mf][nf][3] * al[mf][1];
                y2 = (y2 > 0.f) ? y2 : pw * y2;
                y3 = (y3 > 0.f) ? y3 : pw * y3;
                ob[(size_t)(c0 + 8) * LOUT_ + lp] = fmaxf(y2, y3);
            }
        }
        cur ^= 1;
    }
}

// ---------------- launch ----------------
extern "C" void kernel_launch(void* const* d_in, const int* in_sizes, int n_in,
                              void* d_out, int out_size)
{
    const float* I        = (const float*)d_in[0];
    const float* bn_gamma = (const float*)d_in[1];
    const float* bn_beta  = (const float*)d_in[2];
    const float* bn_mean  = (const float*)d_in[3];
    const float* bn_var   = (const float*)d_in[4];
    const float* conv_w   = (const float*)d_in[5];
    const float* alpha    = (const float*)d_in[6];
    const float* prelu_w  = (const float*)d_in[7];
    float* out = (float*)d_out;

    bn_sign_kernel<<<dim3(L_ / 128, B_), 256>>>(I, bn_gamma, bn_beta,
                                                bn_mean, bn_var);

    cudaFuncSetAttribute(conv_gemm_kernel,
                         cudaFuncAttributeMaxDynamicSharedMemorySize, SM_TOTAL);
    conv_gemm_kernel<<<GRID, NTHR, SM_TOTAL>>>(conv_w, alpha, prelu_w, out);
}